// round 13
// baseline (speedup 1.0000x reference)
// R13: resubmission of R12 (container-level failure, audit clean — see theory).
#include <cuda_runtime.h>
#include <cuda_bf16.h>
#include <cstdint>

// ---------------------------------------------------------------- constants
constexpr int B_   = 16;
constexpr int CIN  = 128;
constexpr int H_   = 64;
constexpr int W_   = 64;
constexpr int COUT = 256;
constexpr int HW   = H_ * W_;        // 4096
constexpr int KD   = CIN * 9;        // 1152
constexpr int NPIX = B_ * HW;        // 65536

constexpr int KB16 = KD / 16;        // 72 k16-blocks
constexpr int NCHUNK = 36;           // k32 chunks

// ---------------------------------------------------------------- scratch
__device__ __align__(1024) float    g_off[B_ * 18 * HW];
__device__ __align__(1024) uint32_t g_Ahi[KB16 * 16 * 32 * 4];   // [kb][mb16][lane][reg4]
__device__ __align__(1024) uint32_t g_Alo[KB16 * 16 * 32 * 4];

// ---------------------------------------------------------------- helpers
__device__ __forceinline__ uint32_t smem_u32(const void* p) {
    uint32_t a;
    asm("{ .reg .u64 t; cvta.to.shared.u64 t, %1; cvt.u32.u64 %0, t; }" : "=r"(a) : "l"(p));
    return a;
}
#define CPA16(sa, gp) asm volatile("cp.async.cg.shared.global [%0], [%1], 16;" :: "r"(sa), "l"(gp) : "memory")
#define CPA_COMMIT()  asm volatile("cp.async.commit_group;" ::: "memory")

#define LDS128(r0, r1, r2, r3, a) \
    asm volatile("ld.shared.v4.b32 {%0,%1,%2,%3}, [%4];" : "=r"(r0), "=r"(r1), "=r"(r2), "=r"(r3) : "r"(a))
#define LDS64(r0, r1, a) \
    asm volatile("ld.shared.v2.b32 {%0,%1}, [%2];" : "=r"(r0), "=r"(r1) : "r"(a))

#define MMA16816(c, a, b)                                                     \
    asm volatile("mma.sync.aligned.m16n8k16.row.col.f32.bf16.bf16.f32 "       \
        "{%0,%1,%2,%3}, {%4,%5,%6,%7}, {%8,%9}, {%0,%1,%2,%3};"               \
        : "+f"((c)[0]), "+f"((c)[1]), "+f"((c)[2]), "+f"((c)[3])              \
        : "r"((a)[0]), "r"((a)[1]), "r"((a)[2]), "r"((a)[3]),                 \
          "r"((b)[0]), "r"((b)[1]))

__device__ __forceinline__ uint32_t pack_bf2(__nv_bfloat16 lo_k, __nv_bfloat16 hi_k) {
    __nv_bfloat162 t;
    t.x = lo_k;
    t.y = hi_k;
    return *(uint32_t*)&t;
}

// ---------------------------------------------------------------------------
// Kernel 0: weight prep — bf16 hi/lo split, fragment-ready layout, K=tap*128+c
// ---------------------------------------------------------------------------
__global__ void wprep_kernel(const float* __restrict__ w_def)
{
    const int idx = blockIdx.x * blockDim.x + threadIdx.x;
    if (idx >= COUT * KD) return;
    const int o   = idx / KD;
    const int r   = idx % KD;          // c*9 + tap
    const int c   = r / 9;
    const int tap = r % 9;

    const float w = w_def[idx];
    const __nv_bfloat16 hi = __float2bfloat16_rn(w);
    const __nv_bfloat16 lo = __float2bfloat16_rn(w - __bfloat162float(hi));

    const int knew = tap * 128 + c;
    const int kb = knew >> 4, kk = knew & 15;
    const int mb = o >> 4,    mr = o & 15;
    const int lane = (mr & 7) * 4 + ((kk & 7) >> 1);
    const int reg  = (mr >> 3) + ((kk >> 3) << 1);
    const size_t u16i = ((((size_t)kb * 16 + mb) * 32 + lane) * 4 + reg) * 2 + (kk & 1);

    ((unsigned short*)g_Ahi)[u16i] = *(const unsigned short*)&hi;
    ((unsigned short*)g_Alo)[u16i] = *(const unsigned short*)&lo;
}

// ---------------------------------------------------------------------------
// Kernel 1: offset conv — 4 pixels/thread, weights broadcast from SMEM
// ---------------------------------------------------------------------------
__global__ __launch_bounds__(128) void off_conv_kernel(const float* __restrict__ x,
                                                       const float* __restrict__ w_off,
                                                       const float* __restrict__ b_off)
{
    extern __shared__ float sw[];     // 18*1152
    const int tid = threadIdx.x;
    for (int i = tid; i < 18 * KD; i += blockDim.x) sw[i] = w_off[i];
    __syncthreads();

    const int p   = blockIdx.x * blockDim.x + tid;
    const int b   = p >> 10;
    const int rem = p & 1023;
    const int ho  = rem >> 4;
    const int wo  = (rem & 15) * 4;

    float acc[18][4];
#pragma unroll
    for (int j = 0; j < 18; j++) {
        const float bj = b_off[j];
#pragma unroll
        for (int q = 0; q < 4; q++) acc[j][q] = bj;
    }

    const float* xb = x + (size_t)b * CIN * HW;
    for (int c = 0; c < CIN; c++) {
        const float* xc = xb + c * HW;
        float r[3][6];
#pragma unroll
        for (int dy = 0; dy < 3; dy++) {
            const int iy = ho - 1 + dy;
            const bool vy = (iy >= 0) && (iy < 64);
#pragma unroll
            for (int dx = 0; dx < 6; dx++) {
                const int ix = wo - 1 + dx;
                r[dy][dx] = (vy && ix >= 0 && ix < 64) ? xc[iy * 64 + ix] : 0.0f;
            }
        }
        const float* swc = sw + c * 9;
#pragma unroll
        for (int ky = 0; ky < 3; ky++)
#pragma unroll
            for (int kx = 0; kx < 3; kx++) {
                const float* wp = swc + ky * 3 + kx;
#pragma unroll
                for (int j = 0; j < 18; j++) {
                    const float wv = wp[j * KD];
#pragma unroll
                    for (int q = 0; q < 4; q++)
                        acc[j][q] += wv * r[ky][kx + q];
                }
            }
    }

    float* ob = g_off + (size_t)b * 18 * HW + ho * 64 + wo;
#pragma unroll
    for (int j = 0; j < 18; j++)
        *(float4*)(ob + j * HW) = make_float4(acc[j][0], acc[j][1], acc[j][2], acc[j][3]);
}

// ---------------------------------------------------------------------------
// Kernel 2: FUSED sampling + 3-term bf16 HMMA GEMM, software-pipelined.
//   CTA: m256 x n128, 512 threads (16 warps, warp m64n32).
//   Per iteration: issue raw gathers (chunk i+1, half) -> MMA q-block (hides
//   L2 latency) -> combine/convert/STS -> next half -> q1 -> A prefetch -> sync.
//   MMA q-block restructured for low live regs: ahi pass (2 terms, per-j b),
//   then alo pass reusing the same a registers.
// SMEM carve (u32 units):
//   [0,24576)      A: 3 slots x [pl2][q2][mb16][lane32][reg4]  (96 KB)
//   [24576,32768)  B: 2 bufs  x [pl2][q2][pb16][lane32][reg2]  (32 KB)
//   [32768,37376)  float4 w[1152]                              (18 KB)
//   [37376,39680)  ushort4 idx[1152]                           ( 9 KB)
// ---------------------------------------------------------------------------
__global__ __launch_bounds__(512, 1) void fused_kernel(const float* __restrict__ x,
                                                       float* __restrict__ out)
{
    extern __shared__ uint32_t smem[];
    uint32_t* sA = smem;
    uint32_t* sB = smem + 24576;
    float4*   sW = (float4*)(smem + 32768);
    ushort4*  sI = (ushort4*)(smem + 37376);

    const int tid  = threadIdx.x;
    const int wid  = tid >> 5;
    const int lane = tid & 31;
    const int P    = blockIdx.x;            // 0..511
    const int gp0  = P * 128;
    const int b    = gp0 >> 12;
    const int hw0  = gp0 & 4095;

    const uint32_t sA_addr = smem_u32(sA);
    const uint32_t sB_addr = smem_u32(sB);

    // ---- phase 0: per-(px,tap) bilinear weights + indices --------------
    for (int e = tid; e < 9 * 128; e += 512) {
        const int tap = e >> 7;
        const int pxl = e & 127;
        const int pix = hw0 + pxl;
        const int ho  = pix >> 6;
        const int wo  = pix & 63;

        const float oy = g_off[((size_t)b * 18 + 2 * tap) * HW + pix];
        const float ox = g_off[((size_t)b * 18 + 2 * tap + 1) * HW + pix];

        const float ys = (float)(ho - 1 + (tap / 3)) + oy;
        const float xs = (float)(wo - 1 + (tap % 3)) + ox;

        const float y0f = floorf(ys), x0f = floorf(xs);
        const float wy1 = ys - y0f,  wx1 = xs - x0f;
        const float wy0 = 1.0f - wy1, wx0 = 1.0f - wx1;

        const int y0 = (int)y0f, x0 = (int)x0f;
        const int y1 = y0 + 1,   x1 = x0 + 1;
        const bool vy0 = (y0 >= 0) && (y0 < H_);
        const bool vy1 = (y1 >= 0) && (y1 < H_);
        const bool vx0 = (x0 >= 0) && (x0 < W_);
        const bool vx1 = (x1 >= 0) && (x1 < W_);

        const int y0c = min(max(y0, 0), H_ - 1), y1c = min(max(y1, 0), H_ - 1);
        const int x0c = min(max(x0, 0), W_ - 1), x1c = min(max(x1, 0), W_ - 1);

        sW[e] = make_float4(wy0 * wx0 * ((vy0 && vx0) ? 1.0f : 0.0f),
                            wy0 * wx1 * ((vy0 && vx1) ? 1.0f : 0.0f),
                            wy1 * wx0 * ((vy1 && vx0) ? 1.0f : 0.0f),
                            wy1 * wx1 * ((vy1 && vx1) ? 1.0f : 0.0f));
        sI[e] = make_ushort4((unsigned short)(y0c * 64 + x0c),
                             (unsigned short)(y0c * 64 + x1c),
                             (unsigned short)(y1c * 64 + x0c),
                             (unsigned short)(y1c * 64 + x1c));
    }

    // sampling geometry (fixed per thread)
    const int pxl   = tid & 127;
    const int chgrp = tid >> 7;        // 0..3 -> 8 channels each
    const int sq    = chgrp >> 1;      // k16 block within chunk
    const int sreg  = chgrp & 1;
    const int spb   = pxl >> 3;
    const int slane = (pxl & 7) * 4;

    const int wm = wid >> 2;     // 0..3 -> m64
    const int wn = wid & 3;      // 0..3 -> n32

    float acc[4][4][4] = {};

    // ---- prologue: A0, A1 in flight ------------------------------------
    {
#pragma unroll
        for (int seg = 0; seg < 4; seg++) {
            const int pl = seg >> 1, q = seg & 1;
            const uint32_t* src = (pl ? g_Alo : g_Ahi) + (size_t)(0 * 2 + q) * 2048 + tid * 4;
            CPA16(sA_addr + (0 * 8192 + seg * 2048) * 4 + tid * 16, src);
        }
        CPA_COMMIT();
#pragma unroll
        for (int seg = 0; seg < 4; seg++) {
            const int pl = seg >> 1, q = seg & 1;
            const uint32_t* src = (pl ? g_Alo : g_Ahi) + (size_t)(1 * 2 + q) * 2048 + tid * 4;
            CPA16(sA_addr + (1 * 8192 + seg * 2048) * 4 + tid * 16, src);
        }
        CPA_COMMIT();
    }

    // publish sW/sI before ANY cross-thread read
    __syncthreads();

    // sample chunk 0 into buffer 0 (direct path, once)
    {
        const int ent = 0 * 128 + pxl;
        const float4  wv = sW[ent];
        const ushort4 iv = sI[ent];
        const int ia = iv.x, ib2 = iv.y, ic = iv.z, id = iv.w;
        const float* xc0 = x + ((size_t)b * CIN + 0 + chgrp * 8) * HW;
        float v[8];
#pragma unroll
        for (int cc = 0; cc < 8; cc++) {
            const float* xc = xc0 + cc * HW;
            v[cc] = xc[ia] * wv.x + xc[ib2] * wv.y + xc[ic] * wv.z + xc[id] * wv.w;
        }
#pragma unroll
        for (int pp = 0; pp < 4; pp++) {
            const float a0 = v[2 * pp], a1 = v[2 * pp + 1];
            const __nv_bfloat16 h0 = __float2bfloat16_rn(a0);
            const __nv_bfloat16 h1 = __float2bfloat16_rn(a1);
            const __nv_bfloat16 l0 = __float2bfloat16_rn(a0 - __bfloat162float(h0));
            const __nv_bfloat16 l1 = __float2bfloat16_rn(a1 - __bfloat162float(h1));
            const int bi = spb * 64 + (slane + pp) * 2 + sreg;
            sB[sq * 1024 + bi]        = pack_bf2(h0, h1);
            sB[2048 + sq * 1024 + bi] = pack_bf2(l0, l1);
        }
    }
    asm volatile("cp.async.wait_group 1;");   // A0 landed (this thread)
    __syncthreads();                          // sB0 + A0 visible to all

    float gl[16];

    for (int i = 0; i < NCHUNK; i++) {
        const int slot = i % 3;
        const int buf  = (i & 1) * 4096;

        // chunk i+1 geometry + issue gathers for thread-channels 0..3
        const int  chu = i + 1;
        const bool has_next = (chu < NCHUNK);
        float4 wv = make_float4(0.f, 0.f, 0.f, 0.f);
        int ia = 0, ib2 = 0, ic = 0, id = 0, ob = 0;
        const float* xg = x;
        if (has_next) {
            const int tap = chu >> 2;
            const int c0  = (chu & 3) * 32;
            ob = (chu & 1) * 4096;
            const int ent = tap * 128 + pxl;
            wv = sW[ent];
            const ushort4 iv = sI[ent];
            ia = iv.x; ib2 = iv.y; ic = iv.z; id = iv.w;
            xg = x + ((size_t)b * CIN + c0 + chgrp * 8) * HW;
#pragma unroll
            for (int cc = 0; cc < 4; cc++) {
                const float* xc = xg + cc * HW;
                gl[cc * 4 + 0] = xc[ia];
                gl[cc * 4 + 1] = xc[ib2];
                gl[cc * 4 + 2] = xc[ic];
                gl[cc * 4 + 3] = xc[id];
            }
        }

#pragma unroll
        for (int q = 0; q < 2; q++) {
            // ---- MMA q-block: ahi pass (2 terms), then alo pass ----
            {
                uint32_t a[4][4];
                const uint32_t abase = sA_addr + (slot * 8192 + q * 2048) * 4;
#pragma unroll
                for (int m = 0; m < 4; m++)
                    LDS128(a[m][0], a[m][1], a[m][2], a[m][3],
                           abase + ((wm * 4 + m) * 128 + lane * 4) * 4);
#pragma unroll
                for (int j = 0; j < 4; j++) {
                    uint32_t bh[2], bl[2];
                    const uint32_t ba = sB_addr + (buf + q * 1024 + (wn * 4 + j) * 64 + lane * 2) * 4;
                    LDS64(bh[0], bh[1], ba);
                    LDS64(bl[0], bl[1], ba + 8192);
#pragma unroll
                    for (int m = 0; m < 4; m++) {
                        MMA16816(acc[m][j], a[m], bh);
                        MMA16816(acc[m][j], a[m], bl);
                    }
                }
                // alo pass (reuse a regs)
#pragma unroll
                for (int m = 0; m < 4; m++)
                    LDS128(a[m][0], a[m][1], a[m][2], a[m][3],
                           abase + 16384 + ((wm * 4 + m) * 128 + lane * 4) * 4);
#pragma unroll
                for (int j = 0; j < 4; j++) {
                    uint32_t bh[2];
                    const uint32_t ba = sB_addr + (buf + q * 1024 + (wn * 4 + j) * 64 + lane * 2) * 4;
                    LDS64(bh[0], bh[1], ba);
#pragma unroll
                    for (int m = 0; m < 4; m++)
                        MMA16816(acc[m][j], a[m], bh);
                }
            }

            // ---- combine/convert/store the gathered half; issue next half ----
            if (has_next) {
                const int hb = q;                    // half processed now
#pragma unroll
                for (int pp = 0; pp < 2; pp++) {
                    const float v0 = gl[(2 * pp) * 4 + 0] * wv.x + gl[(2 * pp) * 4 + 1] * wv.y +
                                     gl[(2 * pp) * 4 + 2] * wv.z + gl[(2 * pp) * 4 + 3] * wv.w;
                    const float v1 = gl[(2 * pp + 1) * 4 + 0] * wv.x + gl[(2 * pp + 1) * 4 + 1] * wv.y +
                                     gl[(2 * pp + 1) * 4 + 2] * wv.z + gl[(2 * pp + 1) * 4 + 3] * wv.w;
                    const __nv_bfloat16 h0 = __float2bfloat16_rn(v0);
                    const __nv_bfloat16 h1 = __float2bfloat16_rn(v1);
                    const __nv_bfloat16 l0 = __float2bfloat16_rn(v0 - __bfloat162float(h0));
                    const __nv_bfloat16 l1 = __float2bfloat16_rn(v1 - __bfloat162float(h1));
                    const int ppg = hb * 2 + pp;     // global pair index 0..3
                    const int bi  = spb * 64 + (slane + ppg) * 2 + sreg;
                    sB[ob + sq * 1024 + bi]        = pack_bf2(h0, h1);
                    sB[ob + 2048 + sq * 1024 + bi] = pack_bf2(l0, l1);
                }
                if (q == 0) {
                    // issue gathers for thread-channels 4..7 (hidden by q=1 MMA)
#pragma unroll
                    for (int cc = 0; cc < 4; cc++) {
                        const float* xc = xg + (4 + cc) * HW;
                        gl[cc * 4 + 0] = xc[ia];
                        gl[cc * 4 + 1] = xc[ib2];
                        gl[cc * 4 + 2] = xc[ic];
                        gl[cc * 4 + 3] = xc[id];
                    }
                }
            }
        }

        // ---- refill A slot (i+2)%3 ----
        if (i + 2 < NCHUNK) {
            const int chu2 = i + 2;
            const int sl2  = chu2 % 3;
#pragma unroll
            for (int seg = 0; seg < 4; seg++) {
                const int pl = seg >> 1, q = seg & 1;
                const uint32_t* src = (pl ? g_Alo : g_Ahi) + (size_t)(chu2 * 2 + q) * 2048 + tid * 4;
                CPA16(sA_addr + (sl2 * 8192 + seg * 2048) * 4 + tid * 16, src);
            }
        }
        CPA_COMMIT();
        asm volatile("cp.async.wait_group 1;");   // A(i+1) landed
        __syncthreads();                          // publish sB/(A i+1); WAR fence
    }

    // ---- epilogue -------------------------------------------------------
#pragma unroll
    for (int m = 0; m < 4; m++) {
        const int m0 = wm * 64 + m * 16 + (lane >> 2);
        float* row1 = out + ((size_t)(b * COUT + m0)) * HW + hw0;
        float* row2 = row1 + (size_t)8 * HW;
#pragma unroll
        for (int j = 0; j < 4; j++) {
            const int n0 = wn * 32 + j * 8 + (lane & 3) * 2;
            *(float2*)(row1 + n0) = make_float2(acc[m][j][0], acc[m][j][1]);
            *(float2*)(row2 + n0) = make_float2(acc[m][j][2], acc[m][j][3]);
        }
    }
}

// ---------------------------------------------------------------------------
extern "C" void kernel_launch(void* const* d_in, const int* in_sizes, int n_in,
                              void* d_out, int out_size)
{
    const float* x     = (const float*)d_in[0];
    const float* w_off = (const float*)d_in[1];
    const float* b_off = (const float*)d_in[2];
    const float* w_def = (const float*)d_in[3];
    float* out = (float*)d_out;

    const int smem_off = 18 * KD * sizeof(float);        // 82944
    cudaFuncSetAttribute(off_conv_kernel,
                         cudaFuncAttributeMaxDynamicSharedMemorySize, smem_off);
    const int smem_fused = 39680 * 4;                    // 158720
    cudaFuncSetAttribute(fused_kernel,
                         cudaFuncAttributeMaxDynamicSharedMemorySize, smem_fused);

    wprep_kernel<<<(COUT * KD + 255) / 256, 256>>>(w_def);
    off_conv_kernel<<<(NPIX / 4) / 128, 128, smem_off>>>(x, w_off, b_off);
    fused_kernel<<<NPIX / 128, 512, smem_fused>>>(x, out);
}

// round 15
// speedup vs baseline: 1.2716x; 1.2716x over previous
// R15: resubmission of R14 (container-level failure; audit clean — 4th
// occurrence of first-submission broker flake, all prior resubmits ran).
#include <cuda_runtime.h>
#include <cuda_bf16.h>
#include <cstdint>

// ---------------------------------------------------------------- constants
constexpr int B_   = 16;
constexpr int CIN  = 128;
constexpr int H_   = 64;
constexpr int W_   = 64;
constexpr int COUT = 256;
constexpr int HW   = H_ * W_;        // 4096
constexpr int KD   = CIN * 9;        // 1152
constexpr int NPIX = B_ * HW;        // 65536

constexpr int KB16 = KD / 16;        // 72 k16-blocks per plane
constexpr int NCH  = 36;             // k32 chunks
constexpr int NPB  = NPIX / 8;       // 8192 pixel-octets

// ---------------------------------------------------------------- scratch
__device__ __align__(1024) float    g_off[B_ * 18 * HW];
__device__ __align__(1024) uint32_t g_Ahi[KB16 * 16 * 32 * 4];
__device__ __align__(1024) uint32_t g_Alo[KB16 * 16 * 32 * 4];
__device__ __align__(1024) uint32_t g_Bhi[(size_t)KB16 * NPB * 32 * 2];
__device__ __align__(1024) uint32_t g_Blo[(size_t)KB16 * NPB * 32 * 2];

// ---------------------------------------------------------------- helpers
__device__ __forceinline__ uint32_t smem_u32(const void* p) {
    uint32_t a;
    asm("{ .reg .u64 t; cvta.to.shared.u64 t, %1; cvt.u32.u64 %0, t; }" : "=r"(a) : "l"(p));
    return a;
}
#define CPA16(sa, gp) asm volatile("cp.async.cg.shared.global [%0], [%1], 16;" :: "r"(sa), "l"(gp) : "memory")
#define CPA_COMMIT()  asm volatile("cp.async.commit_group;" ::: "memory")

#define LDS128(r0, r1, r2, r3, a) \
    asm volatile("ld.shared.v4.b32 {%0,%1,%2,%3}, [%4];" : "=r"(r0), "=r"(r1), "=r"(r2), "=r"(r3) : "r"(a))
#define LDS64(r0, r1, a) \
    asm volatile("ld.shared.v2.b32 {%0,%1}, [%2];" : "=r"(r0), "=r"(r1) : "r"(a))

#define MMA16816(c, a, b)                                                     \
    asm volatile("mma.sync.aligned.m16n8k16.row.col.f32.bf16.bf16.f32 "       \
        "{%0,%1,%2,%3}, {%4,%5,%6,%7}, {%8,%9}, {%0,%1,%2,%3};"               \
        : "+f"((c)[0]), "+f"((c)[1]), "+f"((c)[2]), "+f"((c)[3])              \
        : "r"((a)[0]), "r"((a)[1]), "r"((a)[2]), "r"((a)[3]),                 \
          "r"((b)[0]), "r"((b)[1]))

__device__ __forceinline__ uint32_t pack_bf2(__nv_bfloat16 lo_k, __nv_bfloat16 hi_k) {
    __nv_bfloat162 t;
    t.x = lo_k;
    t.y = hi_k;
    return *(uint32_t*)&t;
}

// ---------------------------------------------------------------------------
// Kernel 0: weight prep — bf16 hi/lo split, fragment-ready layout, K=tap*128+c
// ---------------------------------------------------------------------------
__global__ void wprep_kernel(const float* __restrict__ w_def)
{
    const int idx = blockIdx.x * blockDim.x + threadIdx.x;
    if (idx >= COUT * KD) return;
    const int o   = idx / KD;
    const int r   = idx % KD;          // c*9 + tap
    const int c   = r / 9;
    const int tap = r % 9;

    const float w = w_def[idx];
    const __nv_bfloat16 hi = __float2bfloat16_rn(w);
    const __nv_bfloat16 lo = __float2bfloat16_rn(w - __bfloat162float(hi));

    const int knew = tap * 128 + c;
    const int kb = knew >> 4, kk = knew & 15;
    const int mb = o >> 4,    mr = o & 15;
    const int lane = (mr & 7) * 4 + ((kk & 7) >> 1);
    const int reg  = (mr >> 3) + ((kk >> 3) << 1);
    const size_t u16i = ((((size_t)kb * 16 + mb) * 32 + lane) * 4 + reg) * 2 + (kk & 1);

    ((unsigned short*)g_Ahi)[u16i] = *(const unsigned short*)&hi;
    ((unsigned short*)g_Alo)[u16i] = *(const unsigned short*)&lo;
}

// ---------------------------------------------------------------------------
// Kernel 1: offset conv — 4 pixels/thread, weights broadcast from SMEM
// ---------------------------------------------------------------------------
__global__ __launch_bounds__(128) void off_conv_kernel(const float* __restrict__ x,
                                                       const float* __restrict__ w_off,
                                                       const float* __restrict__ b_off)
{
    extern __shared__ float sw[];     // 18*1152
    const int tid = threadIdx.x;
    for (int i = tid; i < 18 * KD; i += blockDim.x) sw[i] = w_off[i];
    __syncthreads();

    const int p   = blockIdx.x * blockDim.x + tid;
    const int b   = p >> 10;
    const int rem = p & 1023;
    const int ho  = rem >> 4;
    const int wo  = (rem & 15) * 4;

    float acc[18][4];
#pragma unroll
    for (int j = 0; j < 18; j++) {
        const float bj = b_off[j];
#pragma unroll
        for (int q = 0; q < 4; q++) acc[j][q] = bj;
    }

    const float* xb = x + (size_t)b * CIN * HW;
    for (int c = 0; c < CIN; c++) {
        const float* xc = xb + c * HW;
        float r[3][6];
#pragma unroll
        for (int dy = 0; dy < 3; dy++) {
            const int iy = ho - 1 + dy;
            const bool vy = (iy >= 0) && (iy < 64);
#pragma unroll
            for (int dx = 0; dx < 6; dx++) {
                const int ix = wo - 1 + dx;
                r[dy][dx] = (vy && ix >= 0 && ix < 64) ? xc[iy * 64 + ix] : 0.0f;
            }
        }
        const float* swc = sw + c * 9;
#pragma unroll
        for (int ky = 0; ky < 3; ky++)
#pragma unroll
            for (int kx = 0; kx < 3; kx++) {
                const float* wp = swc + ky * 3 + kx;
#pragma unroll
                for (int j = 0; j < 18; j++) {
                    const float wv = wp[j * KD];
#pragma unroll
                    for (int q = 0; q < 4; q++)
                        acc[j][q] += wv * r[ky][kx + q];
                }
            }
    }

    float* ob = g_off + (size_t)b * 18 * HW + ho * 64 + wo;
#pragma unroll
    for (int j = 0; j < 18; j++)
        *(float4*)(ob + j * HW) = make_float4(acc[j][0], acc[j][1], acc[j][2], acc[j][3]);
}

// ---------------------------------------------------------------------------
// Kernel 2: bilinear sampling -> mma-fragment-ready bf16 hi/lo planes
// (c, c+1, c+8, c+9) per group -> one uint2 store per plane   (R6, proven)
// ---------------------------------------------------------------------------
__global__ void sample_kernel(const float* __restrict__ x)
{
    const int b   = blockIdx.z;
    const int tap = blockIdx.y;                              // 0..8
    const int pix = blockIdx.x * blockDim.x + threadIdx.x;   // 0..4095
    const int ho  = pix >> 6;
    const int wo  = pix & 63;

    const float* offb = g_off + ((size_t)b * 18 + 2 * tap) * HW;
    const float oy = offb[pix];
    const float ox = offb[HW + pix];

    const float ys = (float)(ho - 1 + (tap / 3)) + oy;
    const float xs = (float)(wo - 1 + (tap % 3)) + ox;

    const float y0f = floorf(ys), x0f = floorf(xs);
    const float wy1 = ys - y0f,  wx1 = xs - x0f;
    const float wy0 = 1.0f - wy1, wx0 = 1.0f - wx1;

    const int y0 = (int)y0f, x0 = (int)x0f;
    const int y1 = y0 + 1,   x1 = x0 + 1;
    const bool vy0 = (y0 >= 0) && (y0 < H_);
    const bool vy1 = (y1 >= 0) && (y1 < H_);
    const bool vx0 = (x0 >= 0) && (x0 < W_);
    const bool vx1 = (x1 >= 0) && (x1 < W_);

    const int y0c = min(max(y0, 0), H_ - 1), y1c = min(max(y1, 0), H_ - 1);
    const int x0c = min(max(x0, 0), W_ - 1), x1c = min(max(x1, 0), W_ - 1);

    const float w00 = wy0 * wx0 * ((vy0 && vx0) ? 1.0f : 0.0f);
    const float w01 = wy0 * wx1 * ((vy0 && vx1) ? 1.0f : 0.0f);
    const float w10 = wy1 * wx0 * ((vy1 && vx0) ? 1.0f : 0.0f);
    const float w11 = wy1 * wx1 * ((vy1 && vx1) ? 1.0f : 0.0f);

    const int i00 = y0c * 64 + x0c, i01 = y0c * 64 + x1c;
    const int i10 = y1c * 64 + x0c, i11 = y1c * 64 + x1c;

    const float* xb = x + (size_t)b * CIN * HW;

    const int gpix  = b * HW + pix;
    const int pb    = gpix >> 3;
    const int lanen = (gpix & 7) * 4;

#pragma unroll 2
    for (int cb = 0; cb < 8; cb++) {
        const int kb = tap * 8 + cb;
#pragma unroll
        for (int pr = 0; pr < 4; pr++) {
            const int c0 = cb * 16 + pr * 2;
            const float* xa = xb + c0 * HW;
            float v[4];
#pragma unroll
            for (int u = 0; u < 4; u++) {
                const float* xc = xa + ((u >> 1) * 8 + (u & 1)) * HW;  // c0, c0+1, c0+8, c0+9
                v[u] = xc[i00] * w00 + xc[i01] * w01 + xc[i10] * w10 + xc[i11] * w11;
            }
            __nv_bfloat16 h[4], l[4];
#pragma unroll
            for (int u = 0; u < 4; u++) {
                h[u] = __float2bfloat16_rn(v[u]);
                l[u] = __float2bfloat16_rn(v[u] - __bfloat162float(h[u]));
            }
            const int lane = lanen + pr;
            const size_t base = (((size_t)kb * NPB + pb) * 32 + lane) * 2;
            *(uint2*)&g_Bhi[base] = make_uint2(pack_bf2(h[0], h[1]), pack_bf2(h[2], h[3]));
            *(uint2*)&g_Blo[base] = make_uint2(pack_bf2(l[0], l[1]), pack_bf2(l[2], l[3]));
        }
    }
}

// ---------------------------------------------------------------------------
// Kernel 3: bf16 HMMA GEMM, all 3 terms per k32 chunk (unique bytes loaded
// once).  CTA = m128 x n128, 8 warps (warp m64n32).  36 iterations, 3-stage
// ring (32KB/stage), ONE barrier per chunk.
// Stage layout (u32): [Ahi 2q x 1024][Alo ...][Bhi ...][Blo ...] = 8192
// ---------------------------------------------------------------------------
__global__ __launch_bounds__(256) void gemm_kernel(float* __restrict__ out)
{
    extern __shared__ uint32_t smem[];   // 3 * 8192 u32 = 96 KB

    const int tid  = threadIdx.x;
    const int wid  = tid >> 5;
    const int lane = tid & 31;
    const int mhalf = blockIdx.x;        // 0,1 (inner -> L2 reuse of B)
    const int ntile = blockIdx.y;        // 0..511
    const int mb0 = mhalf * 8;
    const int pb0 = ntile * 16;

    const uint32_t sbase = smem_u32(smem);

    auto load_chunk = [&](int c) {
        const int slot = c % 3;
        const int kb   = c * 2;
        const uint32_t d = sbase + slot * 8192 * 4;
#pragma unroll
        for (int q = 0; q < 2; q++) {
            const uint32_t* asrc_h = g_Ahi + ((size_t)(kb + q) * 16 + mb0) * 128 + tid * 4;
            const uint32_t* asrc_l = g_Alo + ((size_t)(kb + q) * 16 + mb0) * 128 + tid * 4;
            const uint32_t* bsrc_h = g_Bhi + ((size_t)(kb + q) * NPB + pb0) * 64 + tid * 4;
            const uint32_t* bsrc_l = g_Blo + ((size_t)(kb + q) * NPB + pb0) * 64 + tid * 4;
            CPA16(d + (q * 1024 + tid * 4) * 4,        asrc_h);
            CPA16(d + (2048 + q * 1024 + tid * 4) * 4, asrc_l);
            CPA16(d + (4096 + q * 1024 + tid * 4) * 4, bsrc_h);
            CPA16(d + (6144 + q * 1024 + tid * 4) * 4, bsrc_l);
        }
        CPA_COMMIT();
    };

    float acc[4][4][4] = {};

    load_chunk(0);
    load_chunk(1);
    asm volatile("cp.async.wait_group 1;");
    __syncthreads();

    const int wmm = wid >> 2;            // 0..1 -> m64
    const int wnn = wid & 3;             // 0..3 -> n32

    for (int i = 0; i < NCH; i++) {
        if (i + 2 < NCH) load_chunk(i + 2);
        else             CPA_COMMIT();
        asm volatile("cp.async.wait_group 1;");

        const uint32_t sb = sbase + (i % 3) * 8192 * 4;

#pragma unroll
        for (int q = 0; q < 2; q++) {
            uint32_t a[4][4];
            const uint32_t abase = sb + (q * 1024) * 4;
            // ---- ahi pass: terms Whi*Shi and Whi*Slo ----
#pragma unroll
            for (int m = 0; m < 4; m++)
                LDS128(a[m][0], a[m][1], a[m][2], a[m][3],
                       abase + ((wmm * 4 + m) * 128 + lane * 4) * 4);
#pragma unroll
            for (int j = 0; j < 4; j++) {
                uint32_t bh[2], bl[2];
                const uint32_t ba = sb + (4096 + q * 1024 + (wnn * 4 + j) * 64 + lane * 2) * 4;
                LDS64(bh[0], bh[1], ba);
                LDS64(bl[0], bl[1], ba + 2048 * 4);
#pragma unroll
                for (int m = 0; m < 4; m++) {
                    MMA16816(acc[m][j], a[m], bh);
                    MMA16816(acc[m][j], a[m], bl);
                }
            }
            // ---- alo pass: term Wlo*Shi (reuse a regs) ----
#pragma unroll
            for (int m = 0; m < 4; m++)
                LDS128(a[m][0], a[m][1], a[m][2], a[m][3],
                       abase + (2048 + (wmm * 4 + m) * 128 + lane * 4) * 4);
#pragma unroll
            for (int j = 0; j < 4; j++) {
                uint32_t bh[2];
                const uint32_t ba = sb + (4096 + q * 1024 + (wnn * 4 + j) * 64 + lane * 2) * 4;
                LDS64(bh[0], bh[1], ba);
#pragma unroll
                for (int m = 0; m < 4; m++)
                    MMA16816(acc[m][j], a[m], bh);
            }
        }
        __syncthreads();   // all warps done with slot i%3 before it's refilled
    }

    // epilogue (R6 layout)
    const int cout_base = mhalf * 128 + wmm * 64;
    const int n_base    = ntile * 128 + wnn * 32;
    const int bidx = n_base >> 12;
    const int hwb  = n_base & 4095;

#pragma unroll
    for (int m = 0; m < 4; m++) {
        const int m0 = cout_base + m * 16 + (lane >> 2);
        float* row1 = out + ((size_t)(bidx * COUT + m0)) * HW + hwb;
        float* row2 = row1 + (size_t)8 * HW;
#pragma unroll
        for (int j = 0; j < 4; j++) {
            const int n0 = j * 8 + (lane & 3) * 2;
            *(float2*)(row1 + n0) = make_float2(acc[m][j][0], acc[m][j][1]);
            *(float2*)(row2 + n0) = make_float2(acc[m][j][2], acc[m][j][3]);
        }
    }
}

// ---------------------------------------------------------------------------
extern "C" void kernel_launch(void* const* d_in, const int* in_sizes, int n_in,
                              void* d_out, int out_size)
{
    const float* x     = (const float*)d_in[0];
    const float* w_off = (const float*)d_in[1];
    const float* b_off = (const float*)d_in[2];
    const float* w_def = (const float*)d_in[3];
    float* out = (float*)d_out;

    const int smem_off = 18 * KD * sizeof(float);        // 82944
    cudaFuncSetAttribute(off_conv_kernel,
                         cudaFuncAttributeMaxDynamicSharedMemorySize, smem_off);
    const int smem_gemm = 3 * 8192 * 4;                  // 98304
    cudaFuncSetAttribute(gemm_kernel,
                         cudaFuncAttributeMaxDynamicSharedMemorySize, smem_gemm);

    wprep_kernel<<<(COUT * KD + 255) / 256, 256>>>(w_def);
    off_conv_kernel<<<(NPIX / 4) / 128, 128, smem_off>>>(x, w_off, b_off);
    sample_kernel<<<dim3(HW / 256, 9, B_), 256>>>(x);
    gemm_kernel<<<dim3(2, NPIX / 128), 256, smem_gemm>>>(out);
}